// round 15
// baseline (speedup 1.0000x reference)
#include <cuda_runtime.h>
#include <cuda_fp16.h>
#include <math.h>
#include <stdint.h>

#define N_NODES 50000
#define N_EDGES 1600000
#define NT      12500       // edge tiles of 128
#define NNT     391         // node tiles of 128

// ---- pitches
#define PB2  272    // fp16 [.][k=128 pad] (ldmatrix layout / E1 pitch)
#define PBEA 48     // fp16 [.][k=16 pad]

// ---- edge-kernel SMEM offsets (bytes), 128-edge tiles (4 CTAs/SM)
#define SM_HDN   0           // 128*272 = 34816 (E1 fp16)
#define SM_EA    34816       // 6144
#define SM_W1C   40960       // 6144
#define SM_SIDX  47104       // 512
#define SM_DIDX  47616       // 516 (128 ints + sentinel) pad to 640
#define SM_EIDX  48256       // 512
#define SMEM_E   48768       // x4 = 195072 <= 227KB

// ---- node1 (P/Q) SMEM offsets (dynamic smem of scannode kernel)
#define NSM_X   0
#define NSM_B0  34816
#define NSM_B1  69632
#define NSM_OUT 104448
#define NSM_B1S 139264
#define SMEM_N  139776

// ---- node2 (GEMM2+LN) SMEM offsets
#define N2_W2   0
#define N2_X    34816
#define N2_OUT  69632        // f32 [128][132]
#define N2_B2   137216
#define N2_GAM  137728
#define N2_BET  138240
#define N2_DEG  138752
#define SMEM_N2 139264

// Invariant: g_hsum and g_deg are ZERO at entry of every kernel_launch call
// (zero-initialized at load; node2_kernel re-zeroes its rows at the end).
__device__ float   g_hsum[(size_t)N_NODES * 128];
__device__ __half  g_pq [(size_t)N_NODES * 256];  // [0:128]=P=h@W1a+b1, [128:256]=Q=h@W1b
__device__ int     g_deg [N_NODES];
__device__ int     g_off [N_NODES];
__device__ int     g_eidx[N_EDGES];

// ---------------------------------------------------------------- helpers
__device__ __forceinline__ uint32_t smem_u32(const void* p) {
    uint32_t a;
    asm("{ .reg .u64 t; cvta.to.shared.u64 t, %1; cvt.u32.u64 %0, t; }"
        : "=r"(a) : "l"(p));
    return a;
}
__device__ __forceinline__ void ldsm4(uint32_t* r, uint32_t addr) {
    asm volatile("ldmatrix.sync.aligned.m8n8.x4.shared.b16 {%0,%1,%2,%3}, [%4];"
                 : "=r"(r[0]), "=r"(r[1]), "=r"(r[2]), "=r"(r[3]) : "r"(addr));
}
__device__ __forceinline__ void mma16816(float* c, const uint32_t* a,
                                         const uint32_t* b) {
    asm volatile("mma.sync.aligned.m16n8k16.row.col.f32.f16.f16.f32 "
                 "{%0,%1,%2,%3}, {%4,%5,%6,%7}, {%8,%9}, {%0,%1,%2,%3};"
                 : "+f"(c[0]), "+f"(c[1]), "+f"(c[2]), "+f"(c[3])
                 : "r"(a[0]), "r"(a[1]), "r"(a[2]), "r"(a[3]),
                   "r"(b[0]), "r"(b[1]));
}
__device__ __forceinline__ uint32_t h2bits(float a, float b) {
    __half2 h = __floats2half2_rn(a, b);
    return *reinterpret_cast<uint32_t*>(&h);
}
// exact-GELU, branch/copysign-free:
//   gelu(v) = relu(v) - 0.5*|v| * p(t) * exp(-s^2),  s = |v|/sqrt(2)
// (A&S 7.1.26 erf; identity exact for both signs; abs err 1.5e-7)
__device__ __forceinline__ float gelu_fast(float v) {
    const float av = fabsf(v);
    const float s  = av * 0.70710678118654752440f;
    float t;
    asm("rcp.approx.f32 %0, %1;" : "=f"(t)
        : "f"(fmaf(0.3275911f, s, 1.0f)));
    const float e = __expf(-s * s);
    float p = fmaf(t, 1.061405429f, -1.453152027f);
    p = fmaf(t, p, 1.421413741f);
    p = fmaf(t, p, -0.284496736f);
    p = fmaf(t, p, 0.254829592f);
    p = p * t;
    const float relu = fmaxf(v, 0.0f);
    return fmaf(av * p, -0.5f * e, relu);
}

template <int NCH>
__device__ __forceinline__ void gemm_pass42(float (&c)[2][8][4],
                                            uint32_t abase, uint32_t amstep,
                                            uint32_t bbase, uint32_t bnstep) {
    #pragma unroll
    for (int kc = 0; kc < NCH; ++kc) {
        uint32_t a[2][4], b[4][4];
        ldsm4(a[0], abase);
        ldsm4(a[1], abase + amstep);
        ldsm4(b[0], bbase);
        ldsm4(b[1], bbase + bnstep);
        ldsm4(b[2], bbase + 2 * bnstep);
        ldsm4(b[3], bbase + 3 * bnstep);
        #pragma unroll
        for (int mt = 0; mt < 2; ++mt)
            #pragma unroll
            for (int j = 0; j < 8; ++j)
                mma16816(c[mt][j], a[mt], &b[j >> 1][(j & 1) * 2]);
        abase += 32;
        bbase += 32;
    }
}

// ---------------------------------------------------------------- launch 1: hist (ILP 8)
__global__ void hist_kernel(const int* __restrict__ dst) {
    const int base = (blockIdx.x * blockDim.x + threadIdx.x) * 8;
    if (base + 7 < N_EDGES) {
        const int4 d0 = *reinterpret_cast<const int4*>(dst + base);
        const int4 d1 = *reinterpret_cast<const int4*>(dst + base + 4);
        atomicAdd(&g_deg[d0.x], 1);
        atomicAdd(&g_deg[d0.y], 1);
        atomicAdd(&g_deg[d0.z], 1);
        atomicAdd(&g_deg[d0.w], 1);
        atomicAdd(&g_deg[d1.x], 1);
        atomicAdd(&g_deg[d1.y], 1);
        atomicAdd(&g_deg[d1.z], 1);
        atomicAdd(&g_deg[d1.w], 1);
    } else {
        for (int e = base; e < N_EDGES; ++e) atomicAdd(&g_deg[dst[e]], 1);
    }
}

// ---------------------------------------------------------------- launch 2:
// block 0 (256 thr): exclusive scan g_deg -> g_off; blocks 1..NNT: node1 P/Q
__global__ __launch_bounds__(256)
void scannode_kernel(const float* __restrict__ h,
                     const float* __restrict__ W1,
                     const float* __restrict__ b1) {
    __shared__ int part[256];
    extern __shared__ char smbuf[];

    if (blockIdx.x == 0) {
        const int t = threadIdx.x;
        const int start = t * 196;
        const int end   = (start + 196 < N_NODES) ? start + 196 : N_NODES;
        int s = 0;
        for (int i = start; i < end; ++i) s += g_deg[i];
        part[t] = s;
        __syncthreads();
        for (int o = 1; o < 256; o <<= 1) {
            int v = (t >= o) ? part[t - o] : 0;
            __syncthreads();
            part[t] += v;
            __syncthreads();
        }
        int run = (t == 0) ? 0 : part[t - 1];
        for (int i = start; i < end; ++i) {
            int d = g_deg[i];
            g_off[i] = run;
            run += d;
        }
        return;
    }

    // ---- node1 body (256 threads) ----
    const uint32_t sb = smem_u32(smbuf);
    float* b1s = reinterpret_cast<float*>(smbuf + NSM_B1S);

    const int t = threadIdx.x, l = t & 31, warp = t >> 5;
    const int wm = warp & 3, wn = warp >> 2;
    const int grow = t & 127, ghf = t >> 7;

    for (int i = t; i < 128 * 128; i += 256) {
        int k = i >> 7, n = i & 127;
        *reinterpret_cast<__half*>(smbuf + NSM_B0 + n * PB2 + k * 2) =
            __float2half_rn(W1[k * 128 + n]);
        *reinterpret_cast<__half*>(smbuf + NSM_B1 + n * PB2 + k * 2) =
            __float2half_rn(W1[(k + 128) * 128 + n]);
    }
    if (t < 128) b1s[t] = b1[t];

    const uint32_t aoff = ((l & 7) + 8 * ((l >> 3) & 1)) * PB2 + (l >> 4) * 16;
    const uint32_t boff = ((l & 7) + 8 * (l >> 4)) * PB2 + ((l >> 3) & 1) * 16;
    const uint32_t aX  = sb + NSM_X + 32 * wm * PB2 + aoff;
    const uint32_t bB0 = sb + NSM_B0 + 64 * wn * PB2 + boff;
    const uint32_t bB1 = sb + NSM_B1 + 64 * wn * PB2 + boff;
    const int rbase = 32 * wm + (l >> 2);
    const int cbase = 64 * wn + 2 * (l & 3);

    const int node = (blockIdx.x - 1) * 128 + grow;
    const int nc = node < N_NODES ? node : N_NODES - 1;

    {
        const float4* ps = reinterpret_cast<const float4*>(
            h + (size_t)nc * 128 + ghf * 64);
        char* xr = smbuf + NSM_X + grow * PB2 + ghf * 128;
        #pragma unroll
        for (int q = 0; q < 16; ++q) {
            float4 v = ps[q];
            *reinterpret_cast<uint2*>(xr + q * 8) =
                make_uint2(h2bits(v.x, v.y), h2bits(v.z, v.w));
        }
    }
    __syncthreads();

    #pragma unroll
    for (int pass = 0; pass < 2; ++pass) {
        float c[2][8][4];
        #pragma unroll
        for (int mt = 0; mt < 2; ++mt)
            #pragma unroll
            for (int j = 0; j < 8; ++j)
                #pragma unroll
                for (int i = 0; i < 4; ++i) c[mt][j][i] = 0.f;
        gemm_pass42<8>(c, aX, 16 * PB2, pass ? bB1 : bB0, 16 * PB2);
        #pragma unroll
        for (int mt = 0; mt < 2; ++mt)
            #pragma unroll
            for (int j = 0; j < 8; ++j) {
                const int col = cbase + 8 * j;
                const float bb0 = pass ? 0.f : b1s[col];
                const float bb1 = pass ? 0.f : b1s[col + 1];
                #pragma unroll
                for (int rh = 0; rh < 2; ++rh) {
                    const int row = rbase + 16 * mt + 8 * rh;
                    *reinterpret_cast<uint32_t*>(
                        smbuf + NSM_OUT + row * PB2 + col * 2) =
                        h2bits(c[mt][j][2 * rh] + bb0, c[mt][j][2 * rh + 1] + bb1);
                }
            }
        __syncthreads();
        if (node < N_NODES) {
            const uint4* os = reinterpret_cast<const uint4*>(
                smbuf + NSM_OUT + grow * PB2 + ghf * 128);
            uint4* po = reinterpret_cast<uint4*>(
                g_pq + (size_t)node * 256 + pass * 128 + ghf * 64);
            #pragma unroll
            for (int q = 0; q < 8; ++q) po[q] = os[q];
        }
        __syncthreads();
    }
}

// ---------------------------------------------------------------- launch 3: fill (ILP 8)
__global__ void fill_kernel(const int* __restrict__ dst) {
    const int base = (blockIdx.x * blockDim.x + threadIdx.x) * 8;
    if (base + 7 < N_EDGES) {
        const int4 d0 = *reinterpret_cast<const int4*>(dst + base);
        const int4 d1 = *reinterpret_cast<const int4*>(dst + base + 4);
        const int p0 = atomicAdd(&g_off[d0.x], 1);
        const int p1 = atomicAdd(&g_off[d0.y], 1);
        const int p2 = atomicAdd(&g_off[d0.z], 1);
        const int p3 = atomicAdd(&g_off[d0.w], 1);
        const int p4 = atomicAdd(&g_off[d1.x], 1);
        const int p5 = atomicAdd(&g_off[d1.y], 1);
        const int p6 = atomicAdd(&g_off[d1.z], 1);
        const int p7 = atomicAdd(&g_off[d1.w], 1);
        g_eidx[p0] = base;
        g_eidx[p1] = base + 1;
        g_eidx[p2] = base + 2;
        g_eidx[p3] = base + 3;
        g_eidx[p4] = base + 4;
        g_eidx[p5] = base + 5;
        g_eidx[p6] = base + 6;
        g_eidx[p7] = base + 7;
    } else {
        for (int e = base; e < N_EDGES; ++e) {
            int p = atomicAdd(&g_off[dst[e]], 1);
            g_eidx[p] = e;
        }
    }
}

// ---------------------------------------------------------------- launch 4: edge (PROFILED)
// 128-edge tiles, 512 threads, 4 CTAs/SM
__global__ __launch_bounds__(512, 4)
void edge_mma_kernel(const int*   __restrict__ src,
                     const int*   __restrict__ dst,
                     const float* __restrict__ ea,
                     const float* __restrict__ W1) {
    extern __shared__ char smbuf[];
    const uint32_t sb = smem_u32(smbuf);
    int* sidx  = reinterpret_cast<int*>(smbuf + SM_SIDX);
    int* didx  = reinterpret_cast<int*>(smbuf + SM_DIDX);   // 129 slots (sentinel)
    int* eidxs = reinterpret_cast<int*>(smbuf + SM_EIDX);

    const int t = threadIdx.x, l = t & 31, warp = t >> 5;
    const int wm = warp & 3, wn = warp >> 2;       // 4x4 warp grid (E1 MMA)

    // ---- stage W1c^T (fp16) ----
    for (int i = t; i < 16 * 128; i += 512) {
        int k = i >> 7, n = i & 127;
        *reinterpret_cast<__half*>(smbuf + SM_W1C + n * PBEA + k * 2) =
            __float2half_rn(W1[(k + 256) * 128 + n]);
    }

    const uint32_t aoff48 = ((l & 7) + 8 * ((l >> 3) & 1)) * PBEA + (l >> 4) * 16;
    const uint32_t boff48 = ((l & 7) + 8 * (l >> 4)) * PBEA + ((l >> 3) & 1) * 16;
    const uint32_t aEA  = sb + SM_EA  + 32 * wm * PBEA + aoff48;   // 32 rows/warp
    const uint32_t bW1C = sb + SM_W1C + 32 * wn * PBEA + boff48;
    const int rbase = 32 * wm + (l >> 2);
    const int cbase = 32 * wn + 2 * (l & 3);

    // reduction lane map: 16 warps x 8 rows; each lane handles 4 consecutive cols
    const int rw = warp;                  // 0..15 row group (8 rows each)
    const int c4 = l * 4;                 // col base (0..124)

    __syncthreads();

    for (int tile = blockIdx.x; tile < NT; tile += gridDim.x) {
        const int e0 = tile << 7;                  // 128 edges/tile
        __syncthreads();
        if (t < 128) {
            const int e = g_eidx[e0 + t];
            eidxs[t] = e;
            sidx[t]  = src[e];
            didx[t]  = dst[e];
        } else if (t == 128) {
            didx[128] = -1;                        // sentinel (safe unconditional load)
        }
        __syncthreads();

        // ---- gather EA (4 thr/row) -> SMEM fp16 ----
        {
            const int row = t >> 2, q4 = t & 3;
            float4 v = reinterpret_cast<const float4*>(
                ea + (size_t)eidxs[row] * 16)[q4];
            *reinterpret_cast<uint2*>(smbuf + SM_EA + row * PBEA + q4 * 8) =
                make_uint2(h2bits(v.x, v.y), h2bits(v.z, v.w));
        }
        __syncthreads();

        // ---- E1 = ea @ W1c^T (K=16), fp16 -> SM_HDN ----
        {
            uint32_t bE1[8];
            ldsm4(&bE1[0], bW1C);
            ldsm4(&bE1[4], bW1C + 16 * PBEA);
            #pragma unroll
            for (int mt = 0; mt < 2; ++mt) {
                uint32_t a[4];
                ldsm4(a, aEA + mt * 16 * PBEA);
                float c[4][4];
                #pragma unroll
                for (int j = 0; j < 4; ++j)
                    #pragma unroll
                    for (int i = 0; i < 4; ++i) c[j][i] = 0.f;
                #pragma unroll
                for (int j = 0; j < 4; ++j)
                    mma16816(c[j], a, &bE1[(j >> 1) * 4 + (j & 1) * 2]);
                #pragma unroll
                for (int j = 0; j < 4; ++j) {
                    const int col = cbase + 8 * j;
                    #pragma unroll
                    for (int rh = 0; rh < 2; ++rh) {
                        const int row = rbase + 16 * mt + 8 * rh;
                        *reinterpret_cast<uint32_t*>(
                            smbuf + SM_HDN + row * PB2 + col * 2) =
                            h2bits(c[j][2 * rh], c[j][2 * rh + 1]);
                    }
                }
            }
        }
        __syncthreads();

        // ---- fused gelu(P[src]+Q[dst]+E1) + segmented reduction -> g_hsum ----
        {
            const char* pqb = reinterpret_cast<const char*>(g_pq);
            float a0 = 0.f, a1 = 0.f, a2 = 0.f, a3 = 0.f;
            int dN = didx[rw * 8];
            #pragma unroll
            for (int r = 0; r < 8; ++r) {
                const int row = rw * 8 + r;
                const int sN  = sidx[row];
                const int dN1 = didx[row + 1];     // sentinel makes this safe
                const uint2 e1 = *reinterpret_cast<const uint2*>(
                    smbuf + SM_HDN + row * PB2 + c4 * 2);
                const uint2 pv = *reinterpret_cast<const uint2*>(
                    pqb + (uint32_t)sN * 512u + (uint32_t)(c4 * 2));
                const uint2 qv = *reinterpret_cast<const uint2*>(
                    pqb + (uint32_t)dN * 512u + 256u + (uint32_t)(c4 * 2));
                const __half2 s0 = __hadd2(
                    __hadd2(*reinterpret_cast<const __half2*>(&pv.x),
                            *reinterpret_cast<const __half2*>(&qv.x)),
                    *reinterpret_cast<const __half2*>(&e1.x));
                const __half2 s1 = __hadd2(
                    __hadd2(*reinterpret_cast<const __half2*>(&pv.y),
                            *reinterpret_cast<const __half2*>(&qv.y)),
                    *reinterpret_cast<const __half2*>(&e1.y));
                const float2 f0 = __half22float2(s0);
                const float2 f1 = __half22float2(s1);
                a0 += gelu_fast(f0.x);
                a1 += gelu_fast(f0.y);
                a2 += gelu_fast(f1.x);
                a3 += gelu_fast(f1.y);
                const bool flush = (r == 7) || (dN != dN1);
                if (flush) {
                    asm volatile("red.global.add.v4.f32 [%0], {%1,%2,%3,%4};"
                                 :: "l"(g_hsum + (size_t)dN * 128 + c4),
                                    "f"(a0), "f"(a1), "f"(a2), "f"(a3)
                                 : "memory");
                    a0 = a1 = a2 = a3 = 0.f;
                }
                dN = dN1;
            }
        }
    }
}

// ---------------------------------------------------------------- launch 5: node2 (+cleanup)
// out = LayerNorm(h + hsum @ W2 + deg*b2); then re-zero own rows of hsum/deg
__global__ __launch_bounds__(256, 1)
void node2_kernel(const float* __restrict__ h,
                  const float* __restrict__ W2,
                  const float* __restrict__ b2,
                  const float* __restrict__ gamma,
                  const float* __restrict__ beta,
                  float* __restrict__ out) {
    extern __shared__ char smbuf[];
    const uint32_t sb = smem_u32(smbuf);
    float* b2s = reinterpret_cast<float*>(smbuf + N2_B2);
    float* gms = reinterpret_cast<float*>(smbuf + N2_GAM);
    float* bts = reinterpret_cast<float*>(smbuf + N2_BET);
    int*   dgs = reinterpret_cast<int*>(smbuf + N2_DEG);
    float* outs = reinterpret_cast<float*>(smbuf + N2_OUT);

    const int t = threadIdx.x, l = t & 31, warp = t >> 5;
    const int wm = warp & 3, wn = warp >> 2;
    const int grow = t & 127, ghf = t >> 7;

    for (int i = t; i < 128 * 128; i += 256) {
        int k = i >> 7, n = i & 127;
        *reinterpret_cast<__half*>(smbuf + N2_W2 + n * PB2 + k * 2) =
            __float2half_rn(W2[i]);
    }
    if (t < 128) { b2s[t] = b2[t]; gms[t] = gamma[t]; bts[t] = beta[t]; }

    const int node = blockIdx.x * 128 + grow;
    const int nc = node < N_NODES ? node : N_NODES - 1;
    if (t >= 128 && t < 256) {
        int nn = blockIdx.x * 128 + (t - 128);
        dgs[t - 128] = (nn < N_NODES) ? g_deg[nn] : 0;
    }

    {
        const float4* ps = reinterpret_cast<const float4*>(
            g_hsum + (size_t)nc * 128 + ghf * 64);
        char* xr = smbuf + N2_X + grow * PB2 + ghf * 128;
        #pragma unroll
        for (int q = 0; q < 16; ++q) {
            float4 v = ps[q];
            *reinterpret_cast<uint2*>(xr + q * 8) =
                make_uint2(h2bits(v.x, v.y), h2bits(v.z, v.w));
        }
    }
    __syncthreads();

    const uint32_t aoff = ((l & 7) + 8 * ((l >> 3) & 1)) * PB2 + (l >> 4) * 16;
    const uint32_t boff = ((l & 7) + 8 * (l >> 4)) * PB2 + ((l >> 3) & 1) * 16;
    const uint32_t aX = sb + N2_X + 32 * wm * PB2 + aoff;
    const uint32_t bW = sb + N2_W2 + 64 * wn * PB2 + boff;
    const int rbase = 32 * wm + (l >> 2);
    const int cbase = 64 * wn + 2 * (l & 3);

    float c[2][8][4];
    #pragma unroll
    for (int mt = 0; mt < 2; ++mt)
        #pragma unroll
        for (int j = 0; j < 8; ++j)
            #pragma unroll
            for (int i = 0; i < 4; ++i) c[mt][j][i] = 0.f;
    gemm_pass42<8>(c, aX, 16 * PB2, bW, 16 * PB2);

    #pragma unroll
    for (int mt = 0; mt < 2; ++mt)
        #pragma unroll
        for (int j = 0; j < 8; ++j) {
            const int col = cbase + 8 * j;
            const float bb0 = b2s[col], bb1 = b2s[col + 1];
            #pragma unroll
            for (int rh = 0; rh < 2; ++rh) {
                const int row = rbase + 16 * mt + 8 * rh;
                const float dg = (float)dgs[row];
                outs[row * 132 + col]     = c[mt][j][2 * rh] + dg * bb0;
                outs[row * 132 + col + 1] = c[mt][j][2 * rh + 1] + dg * bb1;
            }
        }
    __syncthreads();

    for (int r = 0; r < 16; ++r) {
        const int row = warp * 16 + r;
        const int nn = blockIdx.x * 128 + row;
        if (nn >= N_NODES) break;
        const float4 hv = reinterpret_cast<const float4*>(h)[(size_t)nn * 32 + l];
        const float4 av = *reinterpret_cast<const float4*>(outs + row * 132 + l * 4);
        float4 x;
        x.x = hv.x + av.x; x.y = hv.y + av.y;
        x.z = hv.z + av.z; x.w = hv.w + av.w;
        float s = x.x + x.y + x.z + x.w;
        #pragma unroll
        for (int o = 16; o > 0; o >>= 1) s += __shfl_xor_sync(0xffffffffu, s, o);
        const float mu = s * (1.0f / 128.0f);
        const float dx = x.x - mu, dy = x.y - mu, dz = x.z - mu, dw = x.w - mu;
        float q = dx * dx + dy * dy + dz * dz + dw * dw;
        #pragma unroll
        for (int o = 16; o > 0; o >>= 1) q += __shfl_xor_sync(0xffffffffu, q, o);
        const float inv = rsqrtf(q * (1.0f / 128.0f) + 1e-5f);
        float4 o4;
        o4.x = dx * inv * gms[l * 4 + 0] + bts[l * 4 + 0];
        o4.y = dy * inv * gms[l * 4 + 1] + bts[l * 4 + 1];
        o4.z = dz * inv * gms[l * 4 + 2] + bts[l * 4 + 2];
        o4.w = dw * inv * gms[l * 4 + 3] + bts[l * 4 + 3];
        reinterpret_cast<float4*>(out)[(size_t)nn * 32 + l] = o4;
    }

    // ---- cleanup: restore zero-state of this block's hsum rows + deg ----
    {
        const int row0 = blockIdx.x * 128;
        float4* hz = reinterpret_cast<float4*>(g_hsum + (size_t)row0 * 128);
        for (int i = t; i < 128 * 32; i += 256) {
            const int rr = row0 + (i >> 5);
            if (rr < N_NODES) hz[i] = make_float4(0.f, 0.f, 0.f, 0.f);
        }
        if (t < 128) {
            const int nn = row0 + t;
            if (nn < N_NODES) g_deg[nn] = 0;
        }
    }
}

// ----------------------------------------------------------------
extern "C" void kernel_launch(void* const* d_in, const int* in_sizes, int n_in,
                              void* d_out, int out_size) {
    const float* h     = (const float*)d_in[0];
    const int*   src   = (const int*)  d_in[1];
    const int*   dst   = (const int*)  d_in[2];
    const float* ea    = (const float*)d_in[3];
    const float* W1    = (const float*)d_in[4];
    const float* b1    = (const float*)d_in[5];
    const float* W2    = (const float*)d_in[6];
    const float* b2    = (const float*)d_in[7];
    const float* gamma = (const float*)d_in[8];
    const float* beta  = (const float*)d_in[9];
    float*       out   = (float*)d_out;

    static int sm_count = []() {
        int dev = 0, c = 148;
        cudaGetDevice(&dev);
        cudaDeviceGetAttribute(&c, cudaDevAttrMultiProcessorCount, dev);
        return c;
    }();
    static bool attr_ok = []() {
        cudaFuncSetAttribute(edge_mma_kernel,
                             cudaFuncAttributeMaxDynamicSharedMemorySize, SMEM_E);
        cudaFuncSetAttribute(scannode_kernel,
                             cudaFuncAttributeMaxDynamicSharedMemorySize, SMEM_N);
        cudaFuncSetAttribute(node2_kernel,
                             cudaFuncAttributeMaxDynamicSharedMemorySize, SMEM_N2);
        return true;
    }();
    (void)attr_ok;

    hist_kernel<<<(N_EDGES / 8 + 255) / 256, 256>>>(dst);              // 1
    scannode_kernel<<<1 + NNT, 256, SMEM_N>>>(h, W1, b1);              // 2
    fill_kernel<<<(N_EDGES / 8 + 255) / 256, 256>>>(dst);              // 3
    edge_mma_kernel<<<4 * sm_count, 512, SMEM_E>>>(src, dst, ea, W1);  // 4 <- profiled
    node2_kernel<<<NNT, 256, SMEM_N2>>>(h, W2, b2, gamma, beta, out);  // 5
}

// round 16
// speedup vs baseline: 1.3112x; 1.3112x over previous
#include <cuda_runtime.h>
#include <cuda_fp16.h>
#include <math.h>
#include <stdint.h>

#define N_NODES 50000
#define N_EDGES 1600000
#define NT      12500       // edge tiles of 128
#define NNT     391         // node tiles of 128

// ---- pitches
#define PB2  272    // fp16 [.][k=128 pad] (ldmatrix layout / E1 pitch)
#define PBEA 48     // fp16 [.][k=16 pad]

// ---- edge-kernel SMEM offsets (bytes), 128-edge tiles (4 CTAs/SM)
#define SM_HDN   0           // 128*272 = 34816 (E1 fp16)
#define SM_EA    34816       // 6144
#define SM_W1C   40960       // 6144
#define SM_SIDX  47104       // 512
#define SM_DIDX  47616       // 129 ints + pad = 640
#define SMEM_E   48256       // x4 = 193024 <= 227KB

// ---- node1 (P/Q) SMEM offsets (dynamic smem of scannode kernel)
#define NSM_X   0
#define NSM_B0  34816
#define NSM_B1  69632
#define NSM_OUT 104448
#define NSM_B1S 139264
#define SMEM_N  139776

// ---- node2 (GEMM2+LN) SMEM offsets
#define N2_W2   0
#define N2_X    34816
#define N2_OUT  69632        // f32 [128][132]
#define N2_B2   137216
#define N2_GAM  137728
#define N2_BET  138240
#define N2_DEG  138752
#define SMEM_N2 139264

// Invariant: g_hsum and g_deg are ZERO at entry of every kernel_launch call
// (zero-initialized at load; node2_kernel re-zeroes its rows at the end).
__device__ float   g_hsum[(size_t)N_NODES * 128];
__device__ __half  g_pq [(size_t)N_NODES * 256];  // [0:128]=P=h@W1a+b1, [128:256]=Q=h@W1b
__device__ int     g_deg [N_NODES];
__device__ int     g_off [N_NODES];
__device__ int     g_eidx[N_EDGES];

// ---------------------------------------------------------------- helpers
__device__ __forceinline__ uint32_t smem_u32(const void* p) {
    uint32_t a;
    asm("{ .reg .u64 t; cvta.to.shared.u64 t, %1; cvt.u32.u64 %0, t; }"
        : "=r"(a) : "l"(p));
    return a;
}
__device__ __forceinline__ void ldsm4(uint32_t* r, uint32_t addr) {
    asm volatile("ldmatrix.sync.aligned.m8n8.x4.shared.b16 {%0,%1,%2,%3}, [%4];"
                 : "=r"(r[0]), "=r"(r[1]), "=r"(r[2]), "=r"(r[3]) : "r"(addr));
}
__device__ __forceinline__ void mma16816(float* c, const uint32_t* a,
                                         const uint32_t* b) {
    asm volatile("mma.sync.aligned.m16n8k16.row.col.f32.f16.f16.f32 "
                 "{%0,%1,%2,%3}, {%4,%5,%6,%7}, {%8,%9}, {%0,%1,%2,%3};"
                 : "+f"(c[0]), "+f"(c[1]), "+f"(c[2]), "+f"(c[3])
                 : "r"(a[0]), "r"(a[1]), "r"(a[2]), "r"(a[3]),
                   "r"(b[0]), "r"(b[1]));
}
__device__ __forceinline__ uint32_t h2bits(float a, float b) {
    __half2 h = __floats2half2_rn(a, b);
    return *reinterpret_cast<uint32_t*>(&h);
}
// GELU via hardware tanh (5 ops: 2 MUL + 2 FMA + 1 MUFU.TANH).
// tanh-form bias vs exact erf GELU <= ~4e-4 abs (avg ~3e-5) — within the
// 1e-3 tolerance on top of the existing fp16-path error (~4.4e-4).
__device__ __forceinline__ float gelu_fast(float v) {
    const float hv = 0.5f * v;
    const float a  = v * fmaf(v * v, 0.0356774081f, 0.7978845608f);
    float t;
    asm("tanh.approx.f32 %0, %1;" : "=f"(t) : "f"(a));
    return fmaf(t, hv, hv);
}

template <int NCH>
__device__ __forceinline__ void gemm_pass42(float (&c)[2][8][4],
                                            uint32_t abase, uint32_t amstep,
                                            uint32_t bbase, uint32_t bnstep) {
    #pragma unroll
    for (int kc = 0; kc < NCH; ++kc) {
        uint32_t a[2][4], b[4][4];
        ldsm4(a[0], abase);
        ldsm4(a[1], abase + amstep);
        ldsm4(b[0], bbase);
        ldsm4(b[1], bbase + bnstep);
        ldsm4(b[2], bbase + 2 * bnstep);
        ldsm4(b[3], bbase + 3 * bnstep);
        #pragma unroll
        for (int mt = 0; mt < 2; ++mt)
            #pragma unroll
            for (int j = 0; j < 8; ++j)
                mma16816(c[mt][j], a[mt], &b[j >> 1][(j & 1) * 2]);
        abase += 32;
        bbase += 32;
    }
}

// ---------------------------------------------------------------- launch 1: hist (ILP 8)
__global__ void hist_kernel(const int* __restrict__ dst) {
    const int base = (blockIdx.x * blockDim.x + threadIdx.x) * 8;
    if (base + 7 < N_EDGES) {
        const int4 d0 = *reinterpret_cast<const int4*>(dst + base);
        const int4 d1 = *reinterpret_cast<const int4*>(dst + base + 4);
        atomicAdd(&g_deg[d0.x], 1);
        atomicAdd(&g_deg[d0.y], 1);
        atomicAdd(&g_deg[d0.z], 1);
        atomicAdd(&g_deg[d0.w], 1);
        atomicAdd(&g_deg[d1.x], 1);
        atomicAdd(&g_deg[d1.y], 1);
        atomicAdd(&g_deg[d1.z], 1);
        atomicAdd(&g_deg[d1.w], 1);
    } else {
        for (int e = base; e < N_EDGES; ++e) atomicAdd(&g_deg[dst[e]], 1);
    }
}

// ---------------------------------------------------------------- launch 2:
// block 0 (256 thr): exclusive scan g_deg -> g_off; blocks 1..NNT: node1 P/Q
__global__ __launch_bounds__(256)
void scannode_kernel(const float* __restrict__ h,
                     const float* __restrict__ W1,
                     const float* __restrict__ b1) {
    __shared__ int part[256];
    extern __shared__ char smbuf[];

    if (blockIdx.x == 0) {
        const int t = threadIdx.x;
        const int start = t * 196;
        const int end   = (start + 196 < N_NODES) ? start + 196 : N_NODES;
        int s = 0;
        for (int i = start; i < end; ++i) s += g_deg[i];
        part[t] = s;
        __syncthreads();
        for (int o = 1; o < 256; o <<= 1) {
            int v = (t >= o) ? part[t - o] : 0;
            __syncthreads();
            part[t] += v;
            __syncthreads();
        }
        int run = (t == 0) ? 0 : part[t - 1];
        for (int i = start; i < end; ++i) {
            int d = g_deg[i];
            g_off[i] = run;
            run += d;
        }
        return;
    }

    // ---- node1 body (256 threads) ----
    const uint32_t sb = smem_u32(smbuf);
    float* b1s = reinterpret_cast<float*>(smbuf + NSM_B1S);

    const int t = threadIdx.x, l = t & 31, warp = t >> 5;
    const int wm = warp & 3, wn = warp >> 2;
    const int grow = t & 127, ghf = t >> 7;

    for (int i = t; i < 128 * 128; i += 256) {
        int k = i >> 7, n = i & 127;
        *reinterpret_cast<__half*>(smbuf + NSM_B0 + n * PB2 + k * 2) =
            __float2half_rn(W1[k * 128 + n]);
        *reinterpret_cast<__half*>(smbuf + NSM_B1 + n * PB2 + k * 2) =
            __float2half_rn(W1[(k + 128) * 128 + n]);
    }
    if (t < 128) b1s[t] = b1[t];

    const uint32_t aoff = ((l & 7) + 8 * ((l >> 3) & 1)) * PB2 + (l >> 4) * 16;
    const uint32_t boff = ((l & 7) + 8 * (l >> 4)) * PB2 + ((l >> 3) & 1) * 16;
    const uint32_t aX  = sb + NSM_X + 32 * wm * PB2 + aoff;
    const uint32_t bB0 = sb + NSM_B0 + 64 * wn * PB2 + boff;
    const uint32_t bB1 = sb + NSM_B1 + 64 * wn * PB2 + boff;
    const int rbase = 32 * wm + (l >> 2);
    const int cbase = 64 * wn + 2 * (l & 3);

    const int node = (blockIdx.x - 1) * 128 + grow;
    const int nc = node < N_NODES ? node : N_NODES - 1;

    {
        const float4* ps = reinterpret_cast<const float4*>(
            h + (size_t)nc * 128 + ghf * 64);
        char* xr = smbuf + NSM_X + grow * PB2 + ghf * 128;
        #pragma unroll
        for (int q = 0; q < 16; ++q) {
            float4 v = ps[q];
            *reinterpret_cast<uint2*>(xr + q * 8) =
                make_uint2(h2bits(v.x, v.y), h2bits(v.z, v.w));
        }
    }
    __syncthreads();

    #pragma unroll
    for (int pass = 0; pass < 2; ++pass) {
        float c[2][8][4];
        #pragma unroll
        for (int mt = 0; mt < 2; ++mt)
            #pragma unroll
            for (int j = 0; j < 8; ++j)
                #pragma unroll
                for (int i = 0; i < 4; ++i) c[mt][j][i] = 0.f;
        gemm_pass42<8>(c, aX, 16 * PB2, pass ? bB1 : bB0, 16 * PB2);
        #pragma unroll
        for (int mt = 0; mt < 2; ++mt)
            #pragma unroll
            for (int j = 0; j < 8; ++j) {
                const int col = cbase + 8 * j;
                const float bb0 = pass ? 0.f : b1s[col];
                const float bb1 = pass ? 0.f : b1s[col + 1];
                #pragma unroll
                for (int rh = 0; rh < 2; ++rh) {
                    const int row = rbase + 16 * mt + 8 * rh;
                    *reinterpret_cast<uint32_t*>(
                        smbuf + NSM_OUT + row * PB2 + col * 2) =
                        h2bits(c[mt][j][2 * rh] + bb0, c[mt][j][2 * rh + 1] + bb1);
                }
            }
        __syncthreads();
        if (node < N_NODES) {
            const uint4* os = reinterpret_cast<const uint4*>(
                smbuf + NSM_OUT + grow * PB2 + ghf * 128);
            uint4* po = reinterpret_cast<uint4*>(
                g_pq + (size_t)node * 256 + pass * 128 + ghf * 64);
            #pragma unroll
            for (int q = 0; q < 8; ++q) po[q] = os[q];
        }
        __syncthreads();
    }
}

// ---------------------------------------------------------------- launch 3: fill (ILP 8)
__global__ void fill_kernel(const int* __restrict__ dst) {
    const int base = (blockIdx.x * blockDim.x + threadIdx.x) * 8;
    if (base + 7 < N_EDGES) {
        const int4 d0 = *reinterpret_cast<const int4*>(dst + base);
        const int4 d1 = *reinterpret_cast<const int4*>(dst + base + 4);
        const int p0 = atomicAdd(&g_off[d0.x], 1);
        const int p1 = atomicAdd(&g_off[d0.y], 1);
        const int p2 = atomicAdd(&g_off[d0.z], 1);
        const int p3 = atomicAdd(&g_off[d0.w], 1);
        const int p4 = atomicAdd(&g_off[d1.x], 1);
        const int p5 = atomicAdd(&g_off[d1.y], 1);
        const int p6 = atomicAdd(&g_off[d1.z], 1);
        const int p7 = atomicAdd(&g_off[d1.w], 1);
        g_eidx[p0] = base;
        g_eidx[p1] = base + 1;
        g_eidx[p2] = base + 2;
        g_eidx[p3] = base + 3;
        g_eidx[p4] = base + 4;
        g_eidx[p5] = base + 5;
        g_eidx[p6] = base + 6;
        g_eidx[p7] = base + 7;
    } else {
        for (int e = base; e < N_EDGES; ++e) {
            int p = atomicAdd(&g_off[dst[e]], 1);
            g_eidx[p] = e;
        }
    }
}

// ---------------------------------------------------------------- launch 4: edge (PROFILED)
// 128-edge tiles, 512 threads, 4 CTAs/SM; 3 barriers/tile
__global__ __launch_bounds__(512, 4)
void edge_mma_kernel(const int*   __restrict__ src,
                     const int*   __restrict__ dst,
                     const float* __restrict__ ea,
                     const float* __restrict__ W1) {
    extern __shared__ char smbuf[];
    const uint32_t sb = smem_u32(smbuf);
    int* sidx  = reinterpret_cast<int*>(smbuf + SM_SIDX);
    int* didx  = reinterpret_cast<int*>(smbuf + SM_DIDX);   // 129 slots (sentinel)

    const int t = threadIdx.x, l = t & 31, warp = t >> 5;
    const int wm = warp & 3, wn = warp >> 2;       // 4x4 warp grid (E1 MMA)

    // ---- stage W1c^T (fp16) ----
    for (int i = t; i < 16 * 128; i += 512) {
        int k = i >> 7, n = i & 127;
        *reinterpret_cast<__half*>(smbuf + SM_W1C + n * PBEA + k * 2) =
            __float2half_rn(W1[(k + 256) * 128 + n]);
    }

    const uint32_t aoff48 = ((l & 7) + 8 * ((l >> 3) & 1)) * PBEA + (l >> 4) * 16;
    const uint32_t boff48 = ((l & 7) + 8 * (l >> 4)) * PBEA + ((l >> 3) & 1) * 16;
    const uint32_t aEA  = sb + SM_EA  + 32 * wm * PBEA + aoff48;   // 32 rows/warp
    const uint32_t bW1C = sb + SM_W1C + 32 * wn * PBEA + boff48;
    const int rbase = 32 * wm + (l >> 2);
    const int cbase = 32 * wn + 2 * (l & 3);

    // reduction lane map: 16 warps x 8 rows; each lane handles 4 consecutive cols
    const int rw = warp;                  // 0..15 row group (8 rows each)
    const int c4 = l * 4;                 // col base (0..124)
    const uint32_t coff = (uint32_t)(c4 * 2);

    __syncthreads();

    for (int tile = blockIdx.x; tile < NT; tile += gridDim.x) {
        const int e0 = tile << 7;                  // 128 edges/tile
        __syncthreads();                           // A: prev reduction done

        // ---- idx staging + EA gather (concurrent; eidx read straight from GMEM)
        if (t < 128) {
            const int e2 = g_eidx[e0 + t];
            sidx[t] = src[e2];
            didx[t] = dst[e2];
        } else if (t == 128) {
            didx[128] = -1;                        // sentinel
        }
        {
            const int row = t >> 2, q4 = t & 3;
            const int e = g_eidx[e0 + row];        // L1-broadcast across 4 thr
            float4 v = reinterpret_cast<const float4*>(
                ea + (size_t)e * 16)[q4];
            *reinterpret_cast<uint2*>(smbuf + SM_EA + row * PBEA + q4 * 8) =
                make_uint2(h2bits(v.x, v.y), h2bits(v.z, v.w));
        }
        __syncthreads();                           // B: EA + idx visible

        // ---- E1 = ea @ W1c^T (K=16), fp16 -> SM_HDN ----
        {
            uint32_t bE1[8];
            ldsm4(&bE1[0], bW1C);
            ldsm4(&bE1[4], bW1C + 16 * PBEA);
            #pragma unroll
            for (int mt = 0; mt < 2; ++mt) {
                uint32_t a[4];
                ldsm4(a, aEA + mt * 16 * PBEA);
                float c[4][4];
                #pragma unroll
                for (int j = 0; j < 4; ++j)
                    #pragma unroll
                    for (int i = 0; i < 4; ++i) c[j][i] = 0.f;
                #pragma unroll
                for (int j = 0; j < 4; ++j)
                    mma16816(c[j], a, &bE1[(j >> 1) * 4 + (j & 1) * 2]);
                #pragma unroll
                for (int j = 0; j < 4; ++j) {
                    const int col = cbase + 8 * j;
                    #pragma unroll
                    for (int rh = 0; rh < 2; ++rh) {
                        const int row = rbase + 16 * mt + 8 * rh;
                        *reinterpret_cast<uint32_t*>(
                            smbuf + SM_HDN + row * PB2 + col * 2) =
                            h2bits(c[j][2 * rh], c[j][2 * rh + 1]);
                    }
                }
            }
        }
        __syncthreads();                           // C: E1 visible

        // ---- fused gelu(P[src]+Q[dst]+E1) + segmented reduction -> g_hsum ----
        {
            const char* pqb = reinterpret_cast<const char*>(g_pq);
            float a0 = 0.f, a1 = 0.f, a2 = 0.f, a3 = 0.f;
            int dN = didx[rw * 8];
            uint2 qv = *reinterpret_cast<const uint2*>(
                pqb + (uint32_t)dN * 512u + 256u + coff);
            #pragma unroll
            for (int r = 0; r < 8; ++r) {
                const int row = rw * 8 + r;
                const int sN  = sidx[row];
                const int dN1 = didx[row + 1];     // sentinel-safe
                const uint2 e1 = *reinterpret_cast<const uint2*>(
                    smbuf + SM_HDN + row * PB2 + coff);
                const uint2 pv = *reinterpret_cast<const uint2*>(
                    pqb + (uint32_t)sN * 512u + coff);
                const __half2 s0 = __hadd2(
                    __hadd2(*reinterpret_cast<const __half2*>(&pv.x),
                            *reinterpret_cast<const __half2*>(&qv.x)),
                    *reinterpret_cast<const __half2*>(&e1.x));
                const __half2 s1 = __hadd2(
                    __hadd2(*reinterpret_cast<const __half2*>(&pv.y),
                            *reinterpret_cast<const __half2*>(&qv.y)),
                    *reinterpret_cast<const __half2*>(&e1.y));
                const float2 f0 = __half22float2(s0);
                const float2 f1 = __half22float2(s1);
                a0 += gelu_fast(f0.x);
                a1 += gelu_fast(f0.y);
                a2 += gelu_fast(f1.x);
                a3 += gelu_fast(f1.y);
                const bool chg = (dN != dN1);      // warp-uniform
                if (chg || (r == 7)) {
                    asm volatile("red.global.add.v4.f32 [%0], {%1,%2,%3,%4};"
                                 :: "l"(g_hsum + (size_t)dN * 128 + c4),
                                    "f"(a0), "f"(a1), "f"(a2), "f"(a3)
                                 : "memory");
                    a0 = a1 = a2 = a3 = 0.f;
                }
                if (chg && (r < 7)) {
                    qv = *reinterpret_cast<const uint2*>(
                        pqb + (uint32_t)dN1 * 512u + 256u + coff);
                }
                dN = dN1;
            }
        }
    }
}

// ---------------------------------------------------------------- launch 5: node2 (+cleanup)
// out = LayerNorm(h + hsum @ W2 + deg*b2); then re-zero own rows of hsum/deg
__global__ __launch_bounds__(256, 1)
void node2_kernel(const float* __restrict__ h,
                  const float* __restrict__ W2,
                  const float* __restrict__ b2,
                  const float* __restrict__ gamma,
                  const float* __restrict__ beta,
                  float* __restrict__ out) {
    extern __shared__ char smbuf[];
    const uint32_t sb = smem_u32(smbuf);
    float* b2s = reinterpret_cast<float*>(smbuf + N2_B2);
    float* gms = reinterpret_cast<float*>(smbuf + N2_GAM);
    float* bts = reinterpret_cast<float*>(smbuf + N2_BET);
    int*   dgs = reinterpret_cast<int*>(smbuf + N2_DEG);
    float* outs = reinterpret_cast<float*>(smbuf + N2_OUT);

    const int t = threadIdx.x, l = t & 31, warp = t >> 5;
    const int wm = warp & 3, wn = warp >> 2;
    const int grow = t & 127, ghf = t >> 7;

    for (int i = t; i < 128 * 128; i += 256) {
        int k = i >> 7, n = i & 127;
        *reinterpret_cast<__half*>(smbuf + N2_W2 + n * PB2 + k * 2) =
            __float2half_rn(W2[i]);
    }
    if (t < 128) { b2s[t] = b2[t]; gms[t] = gamma[t]; bts[t] = beta[t]; }

    const int node = blockIdx.x * 128 + grow;
    const int nc = node < N_NODES ? node : N_NODES - 1;
    if (t >= 128 && t < 256) {
        int nn = blockIdx.x * 128 + (t - 128);
        dgs[t - 128] = (nn < N_NODES) ? g_deg[nn] : 0;
    }

    {
        const float4* ps = reinterpret_cast<const float4*>(
            g_hsum + (size_t)nc * 128 + ghf * 64);
        char* xr = smbuf + N2_X + grow * PB2 + ghf * 128;
        #pragma unroll
        for (int q = 0; q < 16; ++q) {
            float4 v = ps[q];
            *reinterpret_cast<uint2*>(xr + q * 8) =
                make_uint2(h2bits(v.x, v.y), h2bits(v.z, v.w));
        }
    }
    __syncthreads();

    const uint32_t aoff = ((l & 7) + 8 * ((l >> 3) & 1)) * PB2 + (l >> 4) * 16;
    const uint32_t boff = ((l & 7) + 8 * (l >> 4)) * PB2 + ((l >> 3) & 1) * 16;
    const uint32_t aX = sb + N2_X + 32 * wm * PB2 + aoff;
    const uint32_t bW = sb + N2_W2 + 64 * wn * PB2 + boff;
    const int rbase = 32 * wm + (l >> 2);
    const int cbase = 64 * wn + 2 * (l & 3);

    float c[2][8][4];
    #pragma unroll
    for (int mt = 0; mt < 2; ++mt)
        #pragma unroll
        for (int j = 0; j < 8; ++j)
            #pragma unroll
            for (int i = 0; i < 4; ++i) c[mt][j][i] = 0.f;
    gemm_pass42<8>(c, aX, 16 * PB2, bW, 16 * PB2);

    #pragma unroll
    for (int mt = 0; mt < 2; ++mt)
        #pragma unroll
        for (int j = 0; j < 8; ++j) {
            const int col = cbase + 8 * j;
            const float bb0 = b2s[col], bb1 = b2s[col + 1];
            #pragma unroll
            for (int rh = 0; rh < 2; ++rh) {
                const int row = rbase + 16 * mt + 8 * rh;
                const float dg = (float)dgs[row];
                outs[row * 132 + col]     = c[mt][j][2 * rh] + dg * bb0;
                outs[row * 132 + col + 1] = c[mt][j][2 * rh + 1] + dg * bb1;
            }
        }
    __syncthreads();

    for (int r = 0; r < 16; ++r) {
        const int row = warp * 16 + r;
        const int nn = blockIdx.x * 128 + row;
        if (nn >= N_NODES) break;
        const float4 hv = reinterpret_cast<const float4*>(h)[(size_t)nn * 32 + l];
        const float4 av = *reinterpret_cast<const float4*>(outs + row * 132 + l * 4);
        float4 x;
        x.x = hv.x + av.x; x.y = hv.y + av.y;
        x.z = hv.z + av.z; x.w = hv.w + av.w;
        float s = x.x + x.y + x.z + x.w;
        #pragma unroll
        for (int o = 16; o > 0; o >>= 1) s += __shfl_xor_sync(0xffffffffu, s, o);
        const float mu = s * (1.0f / 128.0f);
        const float dx = x.x - mu, dy = x.y - mu, dz = x.z - mu, dw = x.w - mu;
        float q = dx * dx + dy * dy + dz * dz + dw * dw;
        #pragma unroll
        for (int o = 16; o > 0; o >>= 1) q += __shfl_xor_sync(0xffffffffu, q, o);
        const float inv = rsqrtf(q * (1.0f / 128.0f) + 1e-5f);
        float4 o4;
        o4.x = dx * inv * gms[l * 4 + 0] + bts[l * 4 + 0];
        o4.y = dy * inv * gms[l * 4 + 1] + bts[l * 4 + 1];
        o4.z = dz * inv * gms[l * 4 + 2] + bts[l * 4 + 2];
        o4.w = dw * inv * gms[l * 4 + 3] + bts[l * 4 + 3];
        reinterpret_cast<float4*>(out)[(size_t)nn * 32 + l] = o4;
    }

    // ---- cleanup: restore zero-state of this block's hsum rows + deg ----
    {
        const int row0 = blockIdx.x * 128;
        float4* hz = reinterpret_cast<float4*>(g_hsum + (size_t)row0 * 128);
        for (int i = t; i < 128 * 32; i += 256) {
            const int rr = row0 + (i >> 5);
            if (rr < N_NODES) hz[i] = make_float4(0.f, 0.f, 0.f, 0.f);
        }
        if (t < 128) {
            const int nn = row0 + t;
            if (nn < N_NODES) g_deg[nn] = 0;
        }
    }
}

// ----------------------------------------------------------------
extern "C" void kernel_launch(void* const* d_in, const int* in_sizes, int n_in,
                              void* d_out, int out_size) {
    const float* h     = (const float*)d_in[0];
    const int*   src   = (const int*)  d_in[1];
    const int*   dst   = (const int*)  d_in[2];
    const float* ea    = (const float*)d_in[3];
    const float* W1    = (const float*)d_in[4];
    const float* b1    = (const float*)d_in[5];
    const float* W2    = (const float*)d_in[6];
    const float* b2    = (const float*)d_in[7];
    const float* gamma = (const float*)d_in[8];
    const float* beta  = (const float*)d_in[9];
    float*       out   = (float*)d_out;

    static int sm_count = []() {
        int dev = 0, c = 148;
        cudaGetDevice(&dev);
        cudaDeviceGetAttribute(&c, cudaDevAttrMultiProcessorCount, dev);
        return c;
    }();
    static bool attr_ok = []() {
        cudaFuncSetAttribute(edge_mma_kernel,
                             cudaFuncAttributeMaxDynamicSharedMemorySize, SMEM_E);
        cudaFuncSetAttribute(scannode_kernel,
                             cudaFuncAttributeMaxDynamicSharedMemorySize, SMEM_N);
        cudaFuncSetAttribute(node2_kernel,
                             cudaFuncAttributeMaxDynamicSharedMemorySize, SMEM_N2);
        return true;
    }();
    (void)attr_ok;

    hist_kernel<<<(N_EDGES / 8 + 255) / 256, 256>>>(dst);              // 1
    scannode_kernel<<<1 + NNT, 256, SMEM_N>>>(h, W1, b1);              // 2
    fill_kernel<<<(N_EDGES / 8 + 255) / 256, 256>>>(dst);              // 3
    edge_mma_kernel<<<4 * sm_count, 512, SMEM_E>>>(src, dst, ea, W1);  // 4 <- profiled
    node2_kernel<<<NNT, 256, SMEM_N2>>>(h, W2, b2, gamma, beta, out);  // 5
}

// round 17
// speedup vs baseline: 1.3291x; 1.0137x over previous
#include <cuda_runtime.h>
#include <cuda_fp16.h>
#include <math.h>
#include <stdint.h>

#define N_NODES 50000
#define N_EDGES 1600000
#define NT      12500       // edge tiles of 128
#define NNT     391         // node tiles of 128

// ---- pitches
#define PB2  272    // fp16 [.][k=128 pad] (ldmatrix layout / E1 pitch)
#define PBEA 48     // fp16 [.][k=16 pad]

// ---- edge-kernel SMEM offsets (bytes), 128-edge tiles (4 CTAs/SM)
#define SM_HDN   0           // 128*272 = 34816 (E1 fp16)
#define SM_EA    34816       // 6144
#define SM_W1C   40960       // 6144
#define SM_SIDX  47104       // 512
#define SM_DIDX  47616       // 130 ints + pad = 640
#define SM_TILE  48256       // 4 (dynamic tile index)
#define SMEM_E   48384       // x4 = 193536 <= 227KB

// ---- node1 (P/Q) SMEM offsets: X | B (reused W1a then W1b) | OUT  (2 CTAs/SM)
#define NS_X    0            // 34816
#define NS_B    34816        // 34816
#define NS_OUT  69632        // 34816
#define NS_B1S  104448       // 512
#define SMEM_N  104960

// ---- node2 (GEMM2+LN) SMEM offsets: OUT overlays W2+X after GEMM (3 CTAs/SM)
#define N2_W2   0            // 34816
#define N2_X    34816        // 34816
#define N2_OUT  0            // 67584 (overlay; valid after post-GEMM barrier)
#define N2_B2   69632        // 512
#define N2_GAM  70144        // 512
#define N2_BET  70656        // 512
#define N2_DEG  71168        // 512
#define SMEM_N2 71680

// Invariant: g_hsum, g_deg, g_tile_ctr are ZERO at entry of every launch call
// (zero-init at load; node2 re-zeroes hsum/deg rows; fill resets g_tile_ctr).
__device__ float   g_hsum[(size_t)N_NODES * 128];
__device__ __half  g_pq [(size_t)N_NODES * 256];  // [0:128]=P=h@W1a+b1, [128:256]=Q=h@W1b
__device__ int     g_deg [N_NODES];
__device__ int     g_off [N_NODES];
__device__ int     g_eidx[N_EDGES];
__device__ int     g_tile_ctr;

// ---------------------------------------------------------------- helpers
__device__ __forceinline__ uint32_t smem_u32(const void* p) {
    uint32_t a;
    asm("{ .reg .u64 t; cvta.to.shared.u64 t, %1; cvt.u32.u64 %0, t; }"
        : "=r"(a) : "l"(p));
    return a;
}
__device__ __forceinline__ void ldsm4(uint32_t* r, uint32_t addr) {
    asm volatile("ldmatrix.sync.aligned.m8n8.x4.shared.b16 {%0,%1,%2,%3}, [%4];"
                 : "=r"(r[0]), "=r"(r[1]), "=r"(r[2]), "=r"(r[3]) : "r"(addr));
}
__device__ __forceinline__ void mma16816(float* c, const uint32_t* a,
                                         const uint32_t* b) {
    asm volatile("mma.sync.aligned.m16n8k16.row.col.f32.f16.f16.f32 "
                 "{%0,%1,%2,%3}, {%4,%5,%6,%7}, {%8,%9}, {%0,%1,%2,%3};"
                 : "+f"(c[0]), "+f"(c[1]), "+f"(c[2]), "+f"(c[3])
                 : "r"(a[0]), "r"(a[1]), "r"(a[2]), "r"(a[3]),
                   "r"(b[0]), "r"(b[1]));
}
__device__ __forceinline__ uint32_t h2bits(float a, float b) {
    __half2 h = __floats2half2_rn(a, b);
    return *reinterpret_cast<uint32_t*>(&h);
}
// GELU via hardware tanh (2 MUL + 2 FMA + 1 MUFU.TANH)
__device__ __forceinline__ float gelu_fast(float v) {
    const float hv = 0.5f * v;
    const float a  = v * fmaf(v * v, 0.0356774081f, 0.7978845608f);
    float t;
    asm("tanh.approx.f32 %0, %1;" : "=f"(t) : "f"(a));
    return fmaf(t, hv, hv);
}

template <int NCH>
__device__ __forceinline__ void gemm_pass42(float (&c)[2][8][4],
                                            uint32_t abase, uint32_t amstep,
                                            uint32_t bbase, uint32_t bnstep) {
    #pragma unroll
    for (int kc = 0; kc < NCH; ++kc) {
        uint32_t a[2][4], b[4][4];
        ldsm4(a[0], abase);
        ldsm4(a[1], abase + amstep);
        ldsm4(b[0], bbase);
        ldsm4(b[1], bbase + bnstep);
        ldsm4(b[2], bbase + 2 * bnstep);
        ldsm4(b[3], bbase + 3 * bnstep);
        #pragma unroll
        for (int mt = 0; mt < 2; ++mt)
            #pragma unroll
            for (int j = 0; j < 8; ++j)
                mma16816(c[mt][j], a[mt], &b[j >> 1][(j & 1) * 2]);
        abase += 32;
        bbase += 32;
    }
}

// ---------------------------------------------------------------- launch 1: hist (ILP 8)
__global__ void hist_kernel(const int* __restrict__ dst) {
    const int base = (blockIdx.x * blockDim.x + threadIdx.x) * 8;
    if (base + 7 < N_EDGES) {
        const int4 d0 = *reinterpret_cast<const int4*>(dst + base);
        const int4 d1 = *reinterpret_cast<const int4*>(dst + base + 4);
        atomicAdd(&g_deg[d0.x], 1);
        atomicAdd(&g_deg[d0.y], 1);
        atomicAdd(&g_deg[d0.z], 1);
        atomicAdd(&g_deg[d0.w], 1);
        atomicAdd(&g_deg[d1.x], 1);
        atomicAdd(&g_deg[d1.y], 1);
        atomicAdd(&g_deg[d1.z], 1);
        atomicAdd(&g_deg[d1.w], 1);
    } else {
        for (int e = base; e < N_EDGES; ++e) atomicAdd(&g_deg[dst[e]], 1);
    }
}

// ---------------------------------------------------------------- launch 2:
// block 0 (256 thr): exclusive scan g_deg -> g_off; blocks 1..NNT: node1 P/Q
// node1 uses 3-buffer SMEM (X | B | OUT), restaging B between the two passes
// so 2 CTAs/SM fit.
__global__ __launch_bounds__(256)
void scannode_kernel(const float* __restrict__ h,
                     const float* __restrict__ W1,
                     const float* __restrict__ b1) {
    __shared__ int part[256];
    extern __shared__ char smbuf[];

    if (blockIdx.x == 0) {
        const int t = threadIdx.x;
        const int start = t * 196;
        const int end   = (start + 196 < N_NODES) ? start + 196 : N_NODES;
        int s = 0;
        for (int i = start; i < end; ++i) s += g_deg[i];
        part[t] = s;
        __syncthreads();
        for (int o = 1; o < 256; o <<= 1) {
            int v = (t >= o) ? part[t - o] : 0;
            __syncthreads();
            part[t] += v;
            __syncthreads();
        }
        int run = (t == 0) ? 0 : part[t - 1];
        for (int i = start; i < end; ++i) {
            int d = g_deg[i];
            g_off[i] = run;
            run += d;
        }
        return;
    }

    // ---- node1 body ----
    const uint32_t sb = smem_u32(smbuf);
    float* b1s = reinterpret_cast<float*>(smbuf + NS_B1S);

    const int t = threadIdx.x, l = t & 31, warp = t >> 5;
    const int wm = warp & 3, wn = warp >> 2;
    const int grow = t & 127, ghf = t >> 7;

    const uint32_t aoff = ((l & 7) + 8 * ((l >> 3) & 1)) * PB2 + (l >> 4) * 16;
    const uint32_t boff = ((l & 7) + 8 * (l >> 4)) * PB2 + ((l >> 3) & 1) * 16;
    const uint32_t aX = sb + NS_X + 32 * wm * PB2 + aoff;
    const uint32_t bB = sb + NS_B + 64 * wn * PB2 + boff;
    const int rbase = 32 * wm + (l >> 2);
    const int cbase = 64 * wn + 2 * (l & 3);

    const int node = (blockIdx.x - 1) * 128 + grow;
    const int nc = node < N_NODES ? node : N_NODES - 1;

    // stage X + B=W1a + b1s
    {
        const float4* ps = reinterpret_cast<const float4*>(
            h + (size_t)nc * 128 + ghf * 64);
        char* xr = smbuf + NS_X + grow * PB2 + ghf * 128;
        #pragma unroll
        for (int q = 0; q < 16; ++q) {
            float4 v = ps[q];
            *reinterpret_cast<uint2*>(xr + q * 8) =
                make_uint2(h2bits(v.x, v.y), h2bits(v.z, v.w));
        }
    }
    for (int i = t; i < 128 * 128; i += 256) {
        int k = i >> 7, n = i & 127;
        *reinterpret_cast<__half*>(smbuf + NS_B + n * PB2 + k * 2) =
            __float2half_rn(W1[k * 128 + n]);
    }
    if (t < 128) b1s[t] = b1[t];
    __syncthreads();

    float c[2][8][4];

    // ---- pass 0: P = X@W1a + b1 ----
    #pragma unroll
    for (int mt = 0; mt < 2; ++mt)
        #pragma unroll
        for (int j = 0; j < 8; ++j)
            #pragma unroll
            for (int i = 0; i < 4; ++i) c[mt][j][i] = 0.f;
    gemm_pass42<8>(c, aX, 16 * PB2, bB, 16 * PB2);
    #pragma unroll
    for (int mt = 0; mt < 2; ++mt)
        #pragma unroll
        for (int j = 0; j < 8; ++j) {
            const int col = cbase + 8 * j;
            const float bb0 = b1s[col], bb1 = b1s[col + 1];
            #pragma unroll
            for (int rh = 0; rh < 2; ++rh) {
                const int row = rbase + 16 * mt + 8 * rh;
                *reinterpret_cast<uint32_t*>(
                    smbuf + NS_OUT + row * PB2 + col * 2) =
                    h2bits(c[mt][j][2 * rh] + bb0, c[mt][j][2 * rh + 1] + bb1);
            }
        }
    __syncthreads();

    // write P; restage B=W1b concurrently
    if (node < N_NODES) {
        const uint4* os = reinterpret_cast<const uint4*>(
            smbuf + NS_OUT + grow * PB2 + ghf * 128);
        uint4* po = reinterpret_cast<uint4*>(
            g_pq + (size_t)node * 256 + ghf * 64);
        #pragma unroll
        for (int q = 0; q < 8; ++q) po[q] = os[q];
    }
    for (int i = t; i < 128 * 128; i += 256) {
        int k = i >> 7, n = i & 127;
        *reinterpret_cast<__half*>(smbuf + NS_B + n * PB2 + k * 2) =
            __float2half_rn(W1[(k + 128) * 128 + n]);
    }
    __syncthreads();

    // ---- pass 1: Q = X@W1b ----
    #pragma unroll
    for (int mt = 0; mt < 2; ++mt)
        #pragma unroll
        for (int j = 0; j < 8; ++j)
            #pragma unroll
            for (int i = 0; i < 4; ++i) c[mt][j][i] = 0.f;
    gemm_pass42<8>(c, aX, 16 * PB2, bB, 16 * PB2);
    #pragma unroll
    for (int mt = 0; mt < 2; ++mt)
        #pragma unroll
        for (int j = 0; j < 8; ++j) {
            const int col = cbase + 8 * j;
            #pragma unroll
            for (int rh = 0; rh < 2; ++rh) {
                const int row = rbase + 16 * mt + 8 * rh;
                *reinterpret_cast<uint32_t*>(
                    smbuf + NS_OUT + row * PB2 + col * 2) =
                    h2bits(c[mt][j][2 * rh], c[mt][j][2 * rh + 1]);
            }
        }
    __syncthreads();
    if (node < N_NODES) {
        const uint4* os = reinterpret_cast<const uint4*>(
            smbuf + NS_OUT + grow * PB2 + ghf * 128);
        uint4* po = reinterpret_cast<uint4*>(
            g_pq + (size_t)node * 256 + 128 + ghf * 64);
        #pragma unroll
        for (int q = 0; q < 8; ++q) po[q] = os[q];
    }
}

// ---------------------------------------------------------------- launch 3: fill (ILP 8)
__global__ void fill_kernel(const int* __restrict__ dst) {
    if (blockIdx.x == 0 && threadIdx.x == 0) g_tile_ctr = 0;  // reset for edge
    const int base = (blockIdx.x * blockDim.x + threadIdx.x) * 8;
    if (base + 7 < N_EDGES) {
        const int4 d0 = *reinterpret_cast<const int4*>(dst + base);
        const int4 d1 = *reinterpret_cast<const int4*>(dst + base + 4);
        const int p0 = atomicAdd(&g_off[d0.x], 1);
        const int p1 = atomicAdd(&g_off[d0.y], 1);
        const int p2 = atomicAdd(&g_off[d0.z], 1);
        const int p3 = atomicAdd(&g_off[d0.w], 1);
        const int p4 = atomicAdd(&g_off[d1.x], 1);
        const int p5 = atomicAdd(&g_off[d1.y], 1);
        const int p6 = atomicAdd(&g_off[d1.z], 1);
        const int p7 = atomicAdd(&g_off[d1.w], 1);
        g_eidx[p0] = base;
        g_eidx[p1] = base + 1;
        g_eidx[p2] = base + 2;
        g_eidx[p3] = base + 3;
        g_eidx[p4] = base + 4;
        g_eidx[p5] = base + 5;
        g_eidx[p6] = base + 6;
        g_eidx[p7] = base + 7;
    } else {
        for (int e = base; e < N_EDGES; ++e) {
            int p = atomicAdd(&g_off[dst[e]], 1);
            g_eidx[p] = e;
        }
    }
}

// ---------------------------------------------------------------- launch 4: edge (PROFILED)
// 128-edge tiles, 512 threads, 4 CTAs/SM, dynamic tile stealing
__global__ __launch_bounds__(512, 4)
void edge_mma_kernel(const int*   __restrict__ src,
                     const int*   __restrict__ dst,
                     const float* __restrict__ ea,
                     const float* __restrict__ W1) {
    extern __shared__ char smbuf[];
    const uint32_t sb = smem_u32(smbuf);
    int* sidx  = reinterpret_cast<int*>(smbuf + SM_SIDX);
    int* didx  = reinterpret_cast<int*>(smbuf + SM_DIDX);   // 129 slots (sentinel)
    int* stile = reinterpret_cast<int*>(smbuf + SM_TILE);

    const int t = threadIdx.x, l = t & 31, warp = t >> 5;
    const int wm = warp & 3, wn = warp >> 2;       // 4x4 warp grid (E1 MMA)

    // ---- stage W1c^T (fp16) ----
    for (int i = t; i < 16 * 128; i += 512) {
        int k = i >> 7, n = i & 127;
        *reinterpret_cast<__half*>(smbuf + SM_W1C + n * PBEA + k * 2) =
            __float2half_rn(W1[(k + 256) * 128 + n]);
    }

    const uint32_t aoff48 = ((l & 7) + 8 * ((l >> 3) & 1)) * PBEA + (l >> 4) * 16;
    const uint32_t boff48 = ((l & 7) + 8 * (l >> 4)) * PBEA + ((l >> 3) & 1) * 16;
    const uint32_t aEA  = sb + SM_EA  + 32 * wm * PBEA + aoff48;   // 32 rows/warp
    const uint32_t bW1C = sb + SM_W1C + 32 * wn * PBEA + boff48;
    const int rbase = 32 * wm + (l >> 2);
    const int cbase = 32 * wn + 2 * (l & 3);

    // reduction lane map: 16 warps x 8 rows; each lane handles 4 consecutive cols
    const int rw = warp;
    const int c4 = l * 4;
    const uint32_t coff = (uint32_t)(c4 * 2);

    for (;;) {
        if (t == 0) *stile = atomicAdd(&g_tile_ctr, 1);
        __syncthreads();                           // A: prev reduction done + stile
        const int tile = *stile;
        if (tile >= NT) break;
        const int e0 = tile << 7;                  // 128 edges/tile

        // ---- idx staging + EA gather (eidx read straight from GMEM)
        if (t < 128) {
            const int e2 = g_eidx[e0 + t];
            sidx[t] = src[e2];
            didx[t] = dst[e2];
        } else if (t == 128) {
            didx[128] = -1;                        // sentinel
        }
        {
            const int row = t >> 2, q4 = t & 3;
            const int e = g_eidx[e0 + row];        // L1-broadcast across 4 thr
            float4 v = reinterpret_cast<const float4*>(
                ea + (size_t)e * 16)[q4];
            *reinterpret_cast<uint2*>(smbuf + SM_EA + row * PBEA + q4 * 8) =
                make_uint2(h2bits(v.x, v.y), h2bits(v.z, v.w));
        }
        __syncthreads();                           // B: EA + idx visible

        // ---- E1 = ea @ W1c^T (K=16), fp16 -> SM_HDN ----
        {
            uint32_t bE1[8];
            ldsm4(&bE1[0], bW1C);
            ldsm4(&bE1[4], bW1C + 16 * PBEA);
            #pragma unroll
            for (int mt = 0; mt < 2; ++mt) {
                uint32_t a[4];
                ldsm4(a, aEA + mt * 16 * PBEA);
                float c[4][4];
                #pragma unroll
                for (int j = 0; j < 4; ++j)
                    #pragma unroll
                    for (int i = 0; i < 4; ++i) c[j][i] = 0.f;
                #pragma unroll
                for (int j = 0; j < 4; ++j)
                    mma16816(c[j], a, &bE1[(j >> 1) * 4 + (j & 1) * 2]);
                #pragma unroll
                for (int j = 0; j < 4; ++j) {
                    const int col = cbase + 8 * j;
                    #pragma unroll
                    for (int rh = 0; rh < 2; ++rh) {
                        const int row = rbase + 16 * mt + 8 * rh;
                        *reinterpret_cast<uint32_t*>(
                            smbuf + SM_HDN + row * PB2 + col * 2) =
                            h2bits(c[j][2 * rh], c[j][2 * rh + 1]);
                    }
                }
            }
        }
        __syncthreads();                           // C: E1 visible

        // ---- fused gelu(P[src]+Q[dst]+E1) + segmented reduction -> g_hsum ----
        {
            const char* pqb = reinterpret_cast<const char*>(g_pq);
            float a0 = 0.f, a1 = 0.f, a2 = 0.f, a3 = 0.f;
            int dN = didx[rw * 8];
            uint2 qv = *reinterpret_cast<const uint2*>(
                pqb + (uint32_t)dN * 512u + 256u + coff);
            #pragma unroll
            for (int r = 0; r < 8; ++r) {
                const int row = rw * 8 + r;
                const int sN  = sidx[row];
                const int dN1 = didx[row + 1];     // sentinel-safe
                const uint2 e1 = *reinterpret_cast<const uint2*>(
                    smbuf + SM_HDN + row * PB2 + coff);
                const uint2 pv = *reinterpret_cast<const uint2*>(
                    pqb + (uint32_t)sN * 512u + coff);
                const __half2 s0 = __hadd2(
                    __hadd2(*reinterpret_cast<const __half2*>(&pv.x),
                            *reinterpret_cast<const __half2*>(&qv.x)),
                    *reinterpret_cast<const __half2*>(&e1.x));
                const __half2 s1 = __hadd2(
                    __hadd2(*reinterpret_cast<const __half2*>(&pv.y),
                            *reinterpret_cast<const __half2*>(&qv.y)),
                    *reinterpret_cast<const __half2*>(&e1.y));
                const float2 f0 = __half22float2(s0);
                const float2 f1 = __half22float2(s1);
                a0 += gelu_fast(f0.x);
                a1 += gelu_fast(f0.y);
                a2 += gelu_fast(f1.x);
                a3 += gelu_fast(f1.y);
                const bool chg = (dN != dN1);      // warp-uniform
                if (chg || (r == 7)) {
                    asm volatile("red.global.add.v4.f32 [%0], {%1,%2,%3,%4};"
                                 :: "l"(g_hsum + (size_t)dN * 128 + c4),
                                    "f"(a0), "f"(a1), "f"(a2), "f"(a3)
                                 : "memory");
                    a0 = a1 = a2 = a3 = 0.f;
                }
                if (chg && (r < 7)) {
                    qv = *reinterpret_cast<const uint2*>(
                        pqb + (uint32_t)dN1 * 512u + 256u + coff);
                }
                dN = dN1;
            }
        }
    }
}

// ---------------------------------------------------------------- launch 5: node2 (+cleanup)
// out = LayerNorm(h + hsum @ W2 + deg*b2); OUT overlays W2+X after GEMM barrier
__global__ __launch_bounds__(256, 3)
void node2_kernel(const float* __restrict__ h,
                  const float* __restrict__ W2,
                  const float* __restrict__ b2,
                  const float* __restrict__ gamma,
                  const float* __restrict__ beta,
                  float* __restrict__ out) {
    extern __shared__ char smbuf[];
    const uint32_t sb = smem_u32(smbuf);
    float* b2s = reinterpret_cast<float*>(smbuf + N2_B2);
    float* gms = reinterpret_cast<float*>(smbuf + N2_GAM);
    float* bts = reinterpret_cast<float*>(smbuf + N2_BET);
    int*   dgs = reinterpret_cast<int*>(smbuf + N2_DEG);
    float* outs = reinterpret_cast<float*>(smbuf + N2_OUT);

    const int t = threadIdx.x, l = t & 31, warp = t >> 5;
    const int wm = warp & 3, wn = warp >> 2;
    const int grow = t & 127, ghf = t >> 7;

    for (int i = t; i < 128 * 128; i += 256) {
        int k = i >> 7, n = i & 127;
        *reinterpret_cast<__half*>(smbuf + N2_W2 + n * PB2 + k * 2) =
            __float2half_rn(W2[i]);
    }
    if (t < 128) { b2s[t] = b2[t]; gms[t] = gamma[t]; bts[t] = beta[t]; }

    const int node = blockIdx.x * 128 + grow;
    const int nc = node < N_NODES ? node : N_NODES - 1;
    if (t >= 128 && t < 256) {
        int nn = blockIdx.x * 128 + (t - 128);
        dgs[t - 128] = (nn < N_NODES) ? g_deg[nn] : 0;
    }

    {
        const float4* ps = reinterpret_cast<const float4*>(
            g_hsum + (size_t)nc * 128 + ghf * 64);
        char* xr = smbuf + N2_X + grow * PB2 + ghf * 128;
        #pragma unroll
        for (int q = 0; q < 16; ++q) {
            float4 v = ps[q];
            *reinterpret_cast<uint2*>(xr + q * 8) =
                make_uint2(h2bits(v.x, v.y), h2bits(v.z, v.w));
        }
    }
    __syncthreads();

    const uint32_t aoff = ((l & 7) + 8 * ((l >> 3) & 1)) * PB2 + (l >> 4) * 16;
    const uint32_t boff = ((l & 7) + 8 * (l >> 4)) * PB2 + ((l >> 3) & 1) * 16;
    const uint32_t aX = sb + N2_X + 32 * wm * PB2 + aoff;
    const uint32_t bW = sb + N2_W2 + 64 * wn * PB2 + boff;
    const int rbase = 32 * wm + (l >> 2);
    const int cbase = 64 * wn + 2 * (l & 3);

    float c[2][8][4];
    #pragma unroll
    for (int mt = 0; mt < 2; ++mt)
        #pragma unroll
        for (int j = 0; j < 8; ++j)
            #pragma unroll
            for (int i = 0; i < 4; ++i) c[mt][j][i] = 0.f;
    gemm_pass42<8>(c, aX, 16 * PB2, bW, 16 * PB2);
    __syncthreads();   // all GEMM reads of W2/X done before OUT overlay

    #pragma unroll
    for (int mt = 0; mt < 2; ++mt)
        #pragma unroll
        for (int j = 0; j < 8; ++j) {
            const int col = cbase + 8 * j;
            const float bb0 = b2s[col], bb1 = b2s[col + 1];
            #pragma unroll
            for (int rh = 0; rh < 2; ++rh) {
                const int row = rbase + 16 * mt + 8 * rh;
                const float dg = (float)dgs[row];
                outs[row * 132 + col]     = c[mt][j][2 * rh] + dg * bb0;
                outs[row * 132 + col + 1] = c[mt][j][2 * rh + 1] + dg * bb1;
            }
        }
    __syncthreads();

    for (int r = 0; r < 16; ++r) {
        const int row = warp * 16 + r;
        const int nn = blockIdx.x * 128 + row;
        if (nn >= N_NODES) break;
        const float4 hv = reinterpret_cast<const float4*>(h)[(size_t)nn * 32 + l];
        const float4 av = *reinterpret_cast<const float4*>(outs + row * 132 + l * 4);
        float4 x;
        x.x = hv.x + av.x; x.y = hv.y + av.y;
        x.z = hv.z + av.z; x.w = hv.w + av.w;
        float s = x.x + x.y + x.z + x.w;
        #pragma unroll
        for (int o = 16; o > 0; o >>= 1) s += __shfl_xor_sync(0xffffffffu, s, o);
        const float mu = s * (1.0f / 128.0f);
        const float dx = x.x - mu, dy = x.y - mu, dz = x.z - mu, dw = x.w - mu;
        float q = dx * dx + dy * dy + dz * dz + dw * dw;
        #pragma unroll
        for (int o = 16; o > 0; o >>= 1) q += __shfl_xor_sync(0xffffffffu, q, o);
        const float inv = rsqrtf(q * (1.0f / 128.0f) + 1e-5f);
        float4 o4;
        o4.x = dx * inv * gms[l * 4 + 0] + bts[l * 4 + 0];
        o4.y = dy * inv * gms[l * 4 + 1] + bts[l * 4 + 1];
        o4.z = dz * inv * gms[l * 4 + 2] + bts[l * 4 + 2];
        o4.w = dw * inv * gms[l * 4 + 3] + bts[l * 4 + 3];
        reinterpret_cast<float4*>(out)[(size_t)nn * 32 + l] = o4;
    }

    // ---- cleanup: restore zero-state of this block's hsum rows + deg ----
    {
        const int row0 = blockIdx.x * 128;
        float4* hz = reinterpret_cast<float4*>(g_hsum + (size_t)row0 * 128);
        for (int i = t; i < 128 * 32; i += 256) {
            const int rr = row0 + (i >> 5);
            if (rr < N_NODES) hz[i] = make_float4(0.f, 0.f, 0.f, 0.f);
        }
        if (t < 128) {
            const int nn = row0 + t;
            if (nn < N_NODES) g_deg[nn] = 0;
        }
    }
}

// ----------------------------------------------------------------
extern "C" void kernel_launch(void* const* d_in, const int* in_sizes, int n_in,
                              void* d_out, int out_size) {
    const float* h     = (const float*)d_in[0];
    const int*   src   = (const int*)  d_in[1];
    const int*   dst   = (const int*)  d_in[2];
    const float* ea    = (const float*)d_in[3];
    const float* W1    = (const float*)d_in[4];
    const float* b1    = (const float*)d_in[5];
    const float* W2    = (const float*)d_in[6];
    const float* b2    = (const float*)d_in[7];
    const float* gamma = (const float*)d_in[8];
    const float* beta  = (const float*)d_in[9];
    float*       out   = (float*)d_out;

    static int sm_count = []() {
        int dev = 0, c = 148;
        cudaGetDevice(&dev);
        cudaDeviceGetAttribute(&c, cudaDevAttrMultiProcessorCount, dev);
        return c;
    }();
    static bool attr_ok = []() {
        cudaFuncSetAttribute(edge_mma_kernel,
                             cudaFuncAttributeMaxDynamicSharedMemorySize, SMEM_E);
        cudaFuncSetAttribute(scannode_kernel,
                             cudaFuncAttributeMaxDynamicSharedMemorySize, SMEM_N);
        cudaFuncSetAttribute(node2_kernel,
                             cudaFuncAttributeMaxDynamicSharedMemorySize, SMEM_N2);
        return true;
    }();
    (void)attr_ok;

    hist_kernel<<<(N_EDGES / 8 + 255) / 256, 256>>>(dst);              // 1
    scannode_kernel<<<1 + NNT, 256, SMEM_N>>>(h, W1, b1);              // 2
    fill_kernel<<<(N_EDGES / 8 + 255) / 256, 256>>>(dst);              // 3
    edge_mma_kernel<<<4 * sm_count, 512, SMEM_E>>>(src, dst, ea, W1);  // 4 <- profiled
    node2_kernel<<<NNT, 256, SMEM_N2>>>(h, W2, b2, gamma, beta, out);  // 5
}